// round 8
// baseline (speedup 1.0000x reference)
#include <cuda_runtime.h>
#include <cuda_bf16.h>

#define N_NODES 50000
#define N_EDGES 800000
#define D 64

// Scratch (no allocations allowed): ~25.8 MB of static device globals.
// __align__(16): red.global.add.v4.f32 / float4 ld+st require 16B alignment.
__device__ __align__(16) float g_agg[N_NODES * D];    // scatter-sum of edge_attr
__device__ __align__(16) float g_cnt[N_NODES];        // per-src edge counts
__device__ __align__(16) float g_nemb[N_NODES * D];   // sigmoid node embeddings
__device__ int g_is64;                                 // 1 = edge_index is int64

// ---------------------------------------------------------------------------
// k_detect: decide whether edge_index is int64 or int32.
// int64 indices < 50000 -> every 8B slot has high word == 0.
// int32 index data -> "high words" are random indices, virtually never all 0.
// Deterministic (pure function of input), graph-capturable, single tiny block.
// ---------------------------------------------------------------------------
__global__ void k_detect(const int2* __restrict__ ei) {
    __shared__ int any_hi;
    if (threadIdx.x == 0) any_hi = 0;
    __syncthreads();
    int local = 0;
    for (int i = threadIdx.x; i < 4096; i += blockDim.x)
        local |= ei[i].y;
    if (local) any_hi = 1;            // benign race
    __syncthreads();
    if (threadIdx.x == 0) g_is64 = (any_hi == 0) ? 1 : 0;
}

__device__ __forceinline__ int load_index(const void* ei, int pos, int is64) {
    if (is64) return (int)((const long long*)ei)[pos];
    return ((const int*)ei)[pos];
}

// ---------------------------------------------------------------------------
// k0: zero agg + cnt with float4 stores. 812500 float4s total.
// ---------------------------------------------------------------------------
__global__ void k_zero() {
    int i = blockIdx.x * blockDim.x + threadIdx.x;
    const int AGG4 = (N_NODES * D) / 4;   // 800000
    const int CNT4 = N_NODES / 4;         // 12500
    float4 z = make_float4(0.f, 0.f, 0.f, 0.f);
    if (i < AGG4) {
        reinterpret_cast<float4*>(g_agg)[i] = z;
    } else if (i < AGG4 + CNT4) {
        reinterpret_cast<float4*>(g_cnt)[i - AGG4] = z;
    }
}

// ---------------------------------------------------------------------------
// k1: scatter-add edge_attr rows onto g_agg[src] with vector RED (v4.f32).
// One thread per (edge, 16B chunk): 12.8M threads, 1 float4 load + 1 red.v4.
// g_agg (12.8MB) is L2-resident -> atomics serviced on-die.
// ---------------------------------------------------------------------------
__global__ void k_scatter(const float* __restrict__ edge_attr,
                          const void* __restrict__ edge_index) {
    int idx = blockIdx.x * blockDim.x + threadIdx.x;
    if (idx >= N_EDGES * 16) return;
    int is64 = g_is64;
    int e = idx >> 4;
    int c = idx & 15;
    int src = load_index(edge_index, e, is64);
    if ((unsigned)src >= N_NODES) return;   // safety: never trap
    float4 v = reinterpret_cast<const float4*>(edge_attr)[(size_t)e * 16 + c];
    float* p = &g_agg[src * D + c * 4];
    asm volatile("red.global.add.v4.f32 [%0], {%1,%2,%3,%4};"
                 :: "l"(p), "f"(v.x), "f"(v.y), "f"(v.z), "f"(v.w)
                 : "memory");
    if (c == 0) {
        atomicAdd(&g_cnt[src], 1.0f);   // no return use -> REDG
    }
}

// ---------------------------------------------------------------------------
// k2: per-node: x = node_attr + agg * (0.5/max(cnt,1));
//     nemb = sigmoid(x @ W^T + b)
// Block = 256 threads = 4 nodes x 64 output features. W transposed into smem
// with stride-65 padding (conflict-free column reads).
// ---------------------------------------------------------------------------
__global__ void k_node(const float* __restrict__ node_attr,
                       const float* __restrict__ W,
                       const float* __restrict__ b) {
    __shared__ float wt[64 * 65];   // wt[k*65 + j] = W[j*64 + k]
    __shared__ float xs[4 * 64];
    __shared__ float bs[64];

    int tid = threadIdx.x;
    for (int i = tid; i < 64 * 64; i += 256) {
        int j = i >> 6;
        int k = i & 63;
        wt[k * 65 + j] = W[i];
    }
    if (tid < 64) bs[tid] = b[tid];

    int g = tid >> 6;        // node within block (0..3)
    int j = tid & 63;        // output feature
    int n = blockIdx.x * 4 + g;

    if (n < N_NODES) {
        float cnt = g_cnt[n];
        float inv = 0.5f / fmaxf(cnt, 1.0f);
        xs[g * 64 + j] = node_attr[n * D + j] + g_agg[n * D + j] * inv;
    }
    __syncthreads();

    if (n < N_NODES) {
        float acc = bs[j];
        #pragma unroll
        for (int k = 0; k < 64; k++) {
            acc = fmaf(xs[g * 64 + k], wt[k * 65 + j], acc);
        }
        g_nemb[n * D + j] = 1.0f / (1.0f + __expf(-acc));
    }
}

// ---------------------------------------------------------------------------
// k3: edge output: out[e] = (nemb[src] + nemb[dst]) * 0.5
// One thread per (edge, 16B chunk). nemb is L2-resident; each edge reads full
// 256B rows -> coalesced L2 sector fetches. Output writes coalesced.
// ---------------------------------------------------------------------------
__global__ void k_edge(const void* __restrict__ edge_index,
                       float* __restrict__ out) {
    int idx = blockIdx.x * blockDim.x + threadIdx.x;
    if (idx >= N_EDGES * 16) return;
    int is64 = g_is64;
    int e = idx >> 4;
    int c = idx & 15;
    int src = load_index(edge_index, e, is64);
    int dst = load_index(edge_index, N_EDGES + e, is64);
    float4 a = make_float4(0.f, 0.f, 0.f, 0.f);
    float4 d = a;
    if ((unsigned)src < N_NODES)
        a = reinterpret_cast<const float4*>(g_nemb)[(size_t)src * 16 + c];
    if ((unsigned)dst < N_NODES)
        d = reinterpret_cast<const float4*>(g_nemb)[(size_t)dst * 16 + c];
    float4 o = make_float4((a.x + d.x) * 0.5f,
                           (a.y + d.y) * 0.5f,
                           (a.z + d.z) * 0.5f,
                           (a.w + d.w) * 0.5f);
    reinterpret_cast<float4*>(out)[(size_t)e * 16 + c] = o;
}

// ---------------------------------------------------------------------------
// Inputs identified BY ELEMENT COUNT (robust to metadata ordering):
//   edge_attr  f32     [800000,64] -> 51,200,000
//   edge_index i32/i64 [2,800000]  ->  1,600,000
//   node_attr  f32     [50000,64]  ->  3,200,000
//   W          f32     [64,64]     ->      4,096
//   b          f32     [64]        ->         64
// Output: f32 [800000,64]
// ---------------------------------------------------------------------------
extern "C" void kernel_launch(void* const* d_in, const int* in_sizes, int n_in,
                              void* d_out, int out_size) {
    const float* edge_attr  = nullptr;
    const void*  edge_index = nullptr;
    const float* node_attr  = nullptr;
    const float* W          = nullptr;
    const float* b          = nullptr;

    // If int64 were ever reported as 2x int32 elements (3,200,000), it would
    // collide with node_attr; metadata order puts edge_index before node_attr.
    int c32[4]; int n32 = 0;
    for (int i = 0; i < n_in; i++) {
        switch (in_sizes[i]) {
            case 51200000: edge_attr  = (const float*)d_in[i]; break;
            case 1600000:  edge_index = d_in[i];               break;
            case 3200000:  if (n32 < 4) c32[n32++] = i;        break;
            case 4096:     W          = (const float*)d_in[i]; break;
            case 64:       b          = (const float*)d_in[i]; break;
            default: break;
        }
    }
    if (n32 == 1) {
        node_attr = (const float*)d_in[c32[0]];
    } else if (n32 >= 2) {
        if (!edge_index) { edge_index = d_in[c32[0]]; node_attr = (const float*)d_in[c32[1]]; }
        else             { node_attr  = (const float*)d_in[c32[0]]; }
    }
    float* out = (float*)d_out;

    k_detect<<<1, 256>>>((const int2*)edge_index);

    const int ZERO4 = (N_NODES * D) / 4 + N_NODES / 4;   // 812500
    k_zero<<<(ZERO4 + 255) / 256, 256>>>();

    const int SCAT = N_EDGES * 16;                        // 12.8M
    k_scatter<<<(SCAT + 255) / 256, 256>>>(edge_attr, edge_index);

    k_node<<<(N_NODES + 3) / 4, 256>>>(node_attr, W, b);

    k_edge<<<(SCAT + 255) / 256, 256>>>(edge_index, out);
}

// round 9
// speedup vs baseline: 1.2275x; 1.2275x over previous
#include <cuda_runtime.h>
#include <cuda_bf16.h>

#define N_NODES 50000
#define N_EDGES 800000
#define D 64

// Scratch (no allocations allowed): ~25.8 MB of static device globals.
// __align__(16): red.global.add.v4.f32 / float4 ld+st require 16B alignment.
__device__ __align__(16) float g_agg[N_NODES * D];    // scatter-sum of edge_attr
__device__ __align__(16) float g_cnt[N_NODES];        // per-src edge counts
__device__ __align__(16) float g_nemb[N_NODES * D];   // sigmoid node embeddings
__device__ int g_is64;                                 // 1 = edge_index is int64

// ---------------------------------------------------------------------------
// k_detect: decide whether edge_index is int64 or int32.
// int64 indices < 50000 -> every 8B slot has high word == 0.
// ---------------------------------------------------------------------------
__global__ void k_detect(const int2* __restrict__ ei) {
    __shared__ int any_hi;
    if (threadIdx.x == 0) any_hi = 0;
    __syncthreads();
    int local = 0;
    for (int i = threadIdx.x; i < 4096; i += blockDim.x)
        local |= ei[i].y;
    if (local) any_hi = 1;            // benign race
    __syncthreads();
    if (threadIdx.x == 0) g_is64 = (any_hi == 0) ? 1 : 0;
}

__device__ __forceinline__ int load_index(const void* ei, int pos, int is64) {
    if (is64) return (int)((const long long*)ei)[pos];
    return ((const int*)ei)[pos];
}

// ---------------------------------------------------------------------------
// k0: zero agg + cnt with float4 stores. 812500 float4s total.
// ---------------------------------------------------------------------------
__global__ void k_zero() {
    int i = blockIdx.x * blockDim.x + threadIdx.x;
    const int AGG4 = (N_NODES * D) / 4;   // 800000
    const int CNT4 = N_NODES / 4;         // 12500
    float4 z = make_float4(0.f, 0.f, 0.f, 0.f);
    if (i < AGG4) {
        reinterpret_cast<float4*>(g_agg)[i] = z;
    } else if (i < AGG4 + CNT4) {
        reinterpret_cast<float4*>(g_cnt)[i - AGG4] = z;
    }
}

// ---------------------------------------------------------------------------
// k1: scatter-add edge_attr rows onto g_agg[src] with vector RED (v4.f32).
// One thread per (edge, 16B chunk). g_agg (12.8MB) is L2-resident.
// ---------------------------------------------------------------------------
__global__ void k_scatter(const float* __restrict__ edge_attr,
                          const void* __restrict__ edge_index) {
    int idx = blockIdx.x * blockDim.x + threadIdx.x;
    if (idx >= N_EDGES * 16) return;
    int is64 = g_is64;
    int e = idx >> 4;
    int c = idx & 15;
    int src = load_index(edge_index, e, is64);
    if ((unsigned)src >= N_NODES) return;   // safety: never trap
    float4 v = reinterpret_cast<const float4*>(edge_attr)[(size_t)e * 16 + c];
    float* p = &g_agg[src * D + c * 4];
    asm volatile("red.global.add.v4.f32 [%0], {%1,%2,%3,%4};"
                 :: "l"(p), "f"(v.x), "f"(v.y), "f"(v.z), "f"(v.w)
                 : "memory");
    if (c == 0) {
        atomicAdd(&g_cnt[src], 1.0f);   // no return use -> REDG
    }
}

// ---------------------------------------------------------------------------
// k2: nemb = sigmoid((node_attr + agg*0.5/max(cnt,1)) @ W^T + b)
// Register-tiled GEMM: block = 256 threads = 16 j-groups x 16 node-groups,
// each thread computes a 4x4 (node x feature) tile -> 16 FMA per 8 scalar LDS.
// 64 nodes per block amortize the W smem fill.
//   wt[k][j]  stride-65 pad: conflict-free fill, <=2-way read conflicts.
//   xst[k][n] stride-65 pad: conflict-free transposed fill, <=2-way reads.
// ---------------------------------------------------------------------------
__global__ void __launch_bounds__(256) k_node(const float* __restrict__ node_attr,
                                              const float* __restrict__ W,
                                              const float* __restrict__ b) {
    __shared__ float wt[64 * 65];    // wt[k*65 + j] = W[j*64 + k]
    __shared__ float xst[64 * 65];   // xst[k*65 + n] = x[node nb+n][k]
    __shared__ float bs[64];
    __shared__ float sinv[64];       // 0.5 / max(cnt, 1) per node

    const int tid = threadIdx.x;
    const int nb  = blockIdx.x * 64;          // first node of this block

    // --- fills ---
    if (tid < 64) {
        bs[tid] = b[tid];
        int n_g = nb + tid;
        float cnt = (n_g < N_NODES) ? g_cnt[n_g] : 1.0f;
        sinv[tid] = 0.5f / fmaxf(cnt, 1.0f);
    }
    // W transpose fill: coalesced global read, conflict-free STS (stride 65).
    #pragma unroll
    for (int i = tid; i < 64 * 64; i += 256) {
        int j = i >> 6;
        int k = i & 63;
        wt[k * 65 + j] = W[i];
    }
    __syncthreads();   // sinv ready before x fill uses it

    // x fill (transposed): coalesced global reads, conflict-free STS.
    #pragma unroll
    for (int i = tid; i < 64 * 64; i += 256) {
        int n = i >> 6;
        int k = i & 63;
        int n_g = nb + n;
        float v = 0.0f;
        if (n_g < N_NODES) {
            v = node_attr[n_g * D + k] + g_agg[n_g * D + k] * sinv[n];
        }
        xst[k * 65 + n] = v;
    }
    __syncthreads();

    // --- 4x4 register-tiled GEMM ---
    const int jg = tid & 15;          // feature group
    const int ng = tid >> 4;          // node group
    const int j0 = jg * 4;
    const int n0 = ng * 4;

    float acc[4][4];
    #pragma unroll
    for (int a = 0; a < 4; a++)
        #pragma unroll
        for (int c = 0; c < 4; c++)
            acc[a][c] = bs[j0 + c];

    #pragma unroll 8
    for (int k = 0; k < 64; k++) {
        float xv0 = xst[k * 65 + n0 + 0];
        float xv1 = xst[k * 65 + n0 + 1];
        float xv2 = xst[k * 65 + n0 + 2];
        float xv3 = xst[k * 65 + n0 + 3];
        float wv0 = wt[k * 65 + j0 + 0];
        float wv1 = wt[k * 65 + j0 + 1];
        float wv2 = wt[k * 65 + j0 + 2];
        float wv3 = wt[k * 65 + j0 + 3];
        acc[0][0] = fmaf(xv0, wv0, acc[0][0]); acc[0][1] = fmaf(xv0, wv1, acc[0][1]);
        acc[0][2] = fmaf(xv0, wv2, acc[0][2]); acc[0][3] = fmaf(xv0, wv3, acc[0][3]);
        acc[1][0] = fmaf(xv1, wv0, acc[1][0]); acc[1][1] = fmaf(xv1, wv1, acc[1][1]);
        acc[1][2] = fmaf(xv1, wv2, acc[1][2]); acc[1][3] = fmaf(xv1, wv3, acc[1][3]);
        acc[2][0] = fmaf(xv2, wv0, acc[2][0]); acc[2][1] = fmaf(xv2, wv1, acc[2][1]);
        acc[2][2] = fmaf(xv2, wv2, acc[2][2]); acc[2][3] = fmaf(xv2, wv3, acc[2][3]);
        acc[3][0] = fmaf(xv3, wv0, acc[3][0]); acc[3][1] = fmaf(xv3, wv1, acc[3][1]);
        acc[3][2] = fmaf(xv3, wv2, acc[3][2]); acc[3][3] = fmaf(xv3, wv3, acc[3][3]);
    }

    // sigmoid + vectorized store (each half-warp writes contiguous node rows)
    #pragma unroll
    for (int a = 0; a < 4; a++) {
        int n_g = nb + n0 + a;
        if (n_g < N_NODES) {
            float4 o;
            o.x = 1.0f / (1.0f + __expf(-acc[a][0]));
            o.y = 1.0f / (1.0f + __expf(-acc[a][1]));
            o.z = 1.0f / (1.0f + __expf(-acc[a][2]));
            o.w = 1.0f / (1.0f + __expf(-acc[a][3]));
            *reinterpret_cast<float4*>(&g_nemb[n_g * D + j0]) = o;
        }
    }
}

// ---------------------------------------------------------------------------
// k3: edge output: out[e] = (nemb[src] + nemb[dst]) * 0.5
// One thread per (edge, 16B chunk). nemb is L2-resident; output coalesced.
// ---------------------------------------------------------------------------
__global__ void k_edge(const void* __restrict__ edge_index,
                       float* __restrict__ out) {
    int idx = blockIdx.x * blockDim.x + threadIdx.x;
    if (idx >= N_EDGES * 16) return;
    int is64 = g_is64;
    int e = idx >> 4;
    int c = idx & 15;
    int src = load_index(edge_index, e, is64);
    int dst = load_index(edge_index, N_EDGES + e, is64);
    float4 a = make_float4(0.f, 0.f, 0.f, 0.f);
    float4 d = a;
    if ((unsigned)src < N_NODES)
        a = reinterpret_cast<const float4*>(g_nemb)[(size_t)src * 16 + c];
    if ((unsigned)dst < N_NODES)
        d = reinterpret_cast<const float4*>(g_nemb)[(size_t)dst * 16 + c];
    float4 o = make_float4((a.x + d.x) * 0.5f,
                           (a.y + d.y) * 0.5f,
                           (a.z + d.z) * 0.5f,
                           (a.w + d.w) * 0.5f);
    reinterpret_cast<float4*>(out)[(size_t)e * 16 + c] = o;
}

// ---------------------------------------------------------------------------
// Inputs identified BY ELEMENT COUNT (robust to metadata ordering):
//   edge_attr  f32     [800000,64] -> 51,200,000
//   edge_index i32/i64 [2,800000]  ->  1,600,000
//   node_attr  f32     [50000,64]  ->  3,200,000
//   W          f32     [64,64]     ->      4,096
//   b          f32     [64]        ->         64
// Output: f32 [800000,64]
// ---------------------------------------------------------------------------
extern "C" void kernel_launch(void* const* d_in, const int* in_sizes, int n_in,
                              void* d_out, int out_size) {
    const float* edge_attr  = nullptr;
    const void*  edge_index = nullptr;
    const float* node_attr  = nullptr;
    const float* W          = nullptr;
    const float* b          = nullptr;

    int c32[4]; int n32 = 0;
    for (int i = 0; i < n_in; i++) {
        switch (in_sizes[i]) {
            case 51200000: edge_attr  = (const float*)d_in[i]; break;
            case 1600000:  edge_index = d_in[i];               break;
            case 3200000:  if (n32 < 4) c32[n32++] = i;        break;
            case 4096:     W          = (const float*)d_in[i]; break;
            case 64:       b          = (const float*)d_in[i]; break;
            default: break;
        }
    }
    if (n32 == 1) {
        node_attr = (const float*)d_in[c32[0]];
    } else if (n32 >= 2) {
        if (!edge_index) { edge_index = d_in[c32[0]]; node_attr = (const float*)d_in[c32[1]]; }
        else             { node_attr  = (const float*)d_in[c32[0]]; }
    }
    float* out = (float*)d_out;

    k_detect<<<1, 256>>>((const int2*)edge_index);

    const int ZERO4 = (N_NODES * D) / 4 + N_NODES / 4;   // 812500
    k_zero<<<(ZERO4 + 255) / 256, 256>>>();

    const int SCAT = N_EDGES * 16;                        // 12.8M
    k_scatter<<<(SCAT + 255) / 256, 256>>>(edge_attr, edge_index);

    k_node<<<(N_NODES + 63) / 64, 256>>>(node_attr, W, b);

    k_edge<<<(SCAT + 255) / 256, 256>>>(edge_index, out);
}